// round 6
// baseline (speedup 1.0000x reference)
#include <cuda_runtime.h>
#include <cuda_bf16.h>
#include <cstdint>
#include <cfloat>

// Problem constants
#define NN 65536
#define DD 128
#define MM 8
#define KK 256

#define BM      128
#define THREADS 512            // 16 warps: wr = wid&3 (32-row group), wc = wid>>2 (64-col group)

// smem strides (elements)
#define CB_STRIDE 136          // bf16 codebook row stride (272B: 8-row ldmatrix-free spread)
#define RF_STRIDE 132          // fp32 residual row stride
#define RB_STRIDE 136          // bf16 residual row stride

// smem layout (byte offsets)
#define SM_CB_B    0                                   // 256*136*2 = 69632
#define SM_RF_B    69632                               // 128*132*4 = 67584
#define SM_RB_B    137216                              // 128*136*2 = 34816
#define SM_CSQ_B   172032                              // 256 f
#define SM_RSS_B   173056                              // 128 f
#define SM_CUT_B   173568                              // 128 f
#define SM_MINB_B  174080                              // 128*4 u64 = 4096
#define SM_CAND_B  178176                              // 128 u64 = 1024
#define SM_BYTES   179200

// margin coefficient: >= 3x worst-case bf16 screen error bound (2*2^-7*||r||*||c||)
#define MARG_COEF 0.05f

__device__ __forceinline__ uint32_t ford(float f) {
    uint32_t u = __float_as_uint(f);
    return (u & 0x80000000u) ? ~u : (u | 0x80000000u);
}
__device__ __forceinline__ uint32_t bf16x2_of(float lo, float hi) {
    uint32_t r;  // first source operand -> upper half
    asm("cvt.rn.bf16x2.f32 %0, %1, %2;" : "=r"(r) : "f"(hi), "f"(lo));
    return r;
}
__device__ __forceinline__ void mma_bf16(float& c0, float& c1, float& c2, float& c3,
                                         uint32_t a0, uint32_t a1, uint32_t a2, uint32_t a3,
                                         uint32_t b0, uint32_t b1) {
    asm volatile("mma.sync.aligned.m16n8k16.row.col.f32.bf16.bf16.f32 "
                 "{%0,%1,%2,%3}, {%4,%5,%6,%7}, {%8,%9}, {%0,%1,%2,%3};"
                 : "+f"(c0), "+f"(c1), "+f"(c2), "+f"(c3)
                 : "r"(a0), "r"(a1), "r"(a2), "r"(a3), "r"(b0), "r"(b1));
}

// exact fp32 csq (reference summation order) + per-stage max ||c||, computed once
__device__ float g_csq[MM][KK];
__device__ float g_cmax[MM];

__global__ void csq_prep_kernel(const float* __restrict__ cb) {
    int st = blockIdx.x;
    int k  = threadIdx.x;                  // 256 threads
    const float* row = cb + ((size_t)st * KK + k) * DD;
    float s = 0.f;
    for (int d = 0; d < DD; ++d) { float v = row[d]; s = fmaf(v, v, s); }
    g_csq[st][k] = s;
    __shared__ float red[KK];
    red[k] = s;
    __syncthreads();
    for (int off = 128; off > 0; off >>= 1) {
        if (k < off) red[k] = fmaxf(red[k], red[k + off]);
        __syncthreads();
    }
    if (k == 0) g_cmax[st] = sqrtf(red[0]);
}

__global__ __launch_bounds__(THREADS, 1)
void rq_stage_kernel(const float* __restrict__ x,
                     const float* __restrict__ C,       // stage codebook (K, D) fp32
                     float* __restrict__ codes,
                     float* __restrict__ side,
                     float* __restrict__ xrecon,
                     int stage)
{
    extern __shared__ char smem[];
    __nv_bfloat16* cbB  = (__nv_bfloat16*)(smem + SM_CB_B);
    float*         resF = (float*)(smem + SM_RF_B);
    __nv_bfloat16* resB = (__nv_bfloat16*)(smem + SM_RB_B);
    float*         csq  = (float*)(smem + SM_CSQ_B);
    float*         rss  = (float*)(smem + SM_RSS_B);
    float*         cut  = (float*)(smem + SM_CUT_B);
    unsigned long long* minb = (unsigned long long*)(smem + SM_MINB_B);
    unsigned long long* cand = (unsigned long long*)(smem + SM_CAND_B);

    const int tid  = threadIdx.x;
    const int wid  = tid >> 5;
    const int lane = tid & 31;
    const int rowBase = blockIdx.x * BM;

    const float* prev = (stage == 0) ? nullptr
                                     : (side + (size_t)(stage - 1) * NN * DD);

    // ---- codebook fp32 -> bf16 smem (row-major, stride 136); csq; cand init ----
    #pragma unroll
    for (int j = 0; j < (KK * DD / 2) / THREADS; ++j) {   // 32 pairs/thread
        int idx2 = tid + j * THREADS;
        int k = idx2 >> 6;            // 64 pairs per codeword row
        int dp = idx2 & 63;
        float2 v = *(const float2*)(C + (size_t)k * DD + dp * 2);
        *(uint32_t*)(cbB + k * CB_STRIDE + dp * 2) = bf16x2_of(v.x, v.y);
    }
    if (tid < KK) csq[tid] = g_csq[stage][tid];
    if (tid < BM) cand[tid] = ~0ull;

    // ---- residual tile: fp32 row-major (exact) + bf16 row-major (mma A) + rss ----
    {
        int r  = tid >> 2;
        int c0 = (tid & 3) * 32;
        const float* xrow = x + (size_t)(rowBase + r) * DD + c0;
        const float* prow = prev ? prev + (size_t)(rowBase + r) * DD + c0 : nullptr;
        float part = 0.f;
        #pragma unroll
        for (int j = 0; j < 32; j += 4) {
            float4 xv = *(const float4*)(xrow + j);
            float4 pv = prow ? *(const float4*)(prow + j) : make_float4(0.f,0.f,0.f,0.f);
            float r0 = xv.x - pv.x, r1 = xv.y - pv.y;
            float r2 = xv.z - pv.z, r3 = xv.w - pv.w;
            *(float4*)(resF + r * RF_STRIDE + c0 + j) = make_float4(r0, r1, r2, r3);
            *(uint32_t*)(resB + r * RB_STRIDE + c0 + j)     = bf16x2_of(r0, r1);
            *(uint32_t*)(resB + r * RB_STRIDE + c0 + j + 2) = bf16x2_of(r2, r3);
            part = fmaf(r0, r0, part); part = fmaf(r1, r1, part);
            part = fmaf(r2, r2, part); part = fmaf(r3, r3, part);
        }
        part += __shfl_xor_sync(0xffffffffu, part, 1);
        part += __shfl_xor_sync(0xffffffffu, part, 2);
        if ((tid & 3) == 0) rss[r] = part;
    }
    __syncthreads();

    // ---- GEMM on tensor cores: warp tile 32x64, m16n8k16 bf16 -> f32 ----
    const int wr = wid & 3;           // row group: rows wr*32 .. +31
    const int wc = wid >> 2;          // col group: cols wc*64 .. +63
    const int m_base = wr * 32;
    const int n_base = wc * 64;
    const int qr = lane >> 2;         // 0..7
    const int qc = (lane & 3) * 2;    // 0,2,4,6

    float acc[2][8][4];
    #pragma unroll
    for (int mt = 0; mt < 2; ++mt)
        #pragma unroll
        for (int nt = 0; nt < 8; ++nt)
            #pragma unroll
            for (int c = 0; c < 4; ++c)
                acc[mt][nt][c] = 0.f;

    #pragma unroll
    for (int ks = 0; ks < 8; ++ks) {
        const int k0 = ks * 16;
        uint32_t B[8][2];
        #pragma unroll
        for (int nt = 0; nt < 8; ++nt) {
            int n = n_base + nt * 8 + qr;
            B[nt][0] = *(const uint32_t*)(cbB + n * CB_STRIDE + k0 + qc);
            B[nt][1] = *(const uint32_t*)(cbB + n * CB_STRIDE + k0 + qc + 8);
        }
        uint32_t A[2][4];
        #pragma unroll
        for (int mt = 0; mt < 2; ++mt) {
            int m0 = m_base + mt * 16 + qr;
            A[mt][0] = *(const uint32_t*)(resB + m0 * RB_STRIDE + k0 + qc);
            A[mt][1] = *(const uint32_t*)(resB + (m0 + 8) * RB_STRIDE + k0 + qc);
            A[mt][2] = *(const uint32_t*)(resB + m0 * RB_STRIDE + k0 + qc + 8);
            A[mt][3] = *(const uint32_t*)(resB + (m0 + 8) * RB_STRIDE + k0 + qc + 8);
        }
        #pragma unroll
        for (int mt = 0; mt < 2; ++mt)
            #pragma unroll
            for (int nt = 0; nt < 8; ++nt)
                mma_bf16(acc[mt][nt][0], acc[mt][nt][1], acc[mt][nt][2], acc[mt][nt][3],
                         A[mt][0], A[mt][1], A[mt][2], A[mt][3], B[nt][0], B[nt][1]);
    }

    // Thread owns rows: m_base + mt*16 + h*8 + qr (mt,h in {0,1}),
    // cols: n_base + nt*8 + qc + p; acc element index = h*2 + p.

    // ---- screen pass 1: approx-d2 min per (row, 64-col group) ----
    #pragma unroll
    for (int mt = 0; mt < 2; ++mt) {
        #pragma unroll
        for (int h = 0; h < 2; ++h) {
            int row = m_base + mt * 16 + h * 8 + qr;
            float rv = rss[row];
            unsigned long long best = ~0ull;
            #pragma unroll
            for (int nt = 0; nt < 8; ++nt) {
                #pragma unroll
                for (int p = 0; p < 2; ++p) {
                    int k = n_base + nt * 8 + qc + p;
                    float d2 = __fadd_rn(
                        __fadd_rn(rv, __fmul_rn(-2.f, acc[mt][nt][h * 2 + p])), csq[k]);
                    unsigned long long key =
                        ((unsigned long long)ford(d2) << 32) | (unsigned)k;
                    if (key < best) best = key;
                }
            }
            // reduce across the 4 lanes of the quad (same row)
            unsigned long long o;
            o = __shfl_xor_sync(0xffffffffu, best, 1); if (o < best) best = o;
            o = __shfl_xor_sync(0xffffffffu, best, 2); if (o < best) best = o;
            if ((lane & 3) == 0) minb[row * 4 + wc] = best;
        }
    }
    __syncthreads();

    if (tid < BM) {
        unsigned long long m = minb[tid * 4];
        m = min(m, minb[tid * 4 + 1]);
        m = min(m, minb[tid * 4 + 2]);
        m = min(m, minb[tid * 4 + 3]);
        uint32_t ou = (uint32_t)(m >> 32);
        float amin = __uint_as_float((ou & 0x80000000u) ? (ou & 0x7fffffffu) : ~ou);
        cut[tid] = amin + MARG_COEF * sqrtf(rss[tid]) * g_cmax[stage];
    }
    __syncthreads();

    // ---- pass 2: candidates within margin -> EXACT fp32 rescore (reference order) ----
    #pragma unroll
    for (int mt = 0; mt < 2; ++mt) {
        #pragma unroll
        for (int h = 0; h < 2; ++h) {
            int row = m_base + mt * 16 + h * 8 + qr;
            float rv   = rss[row];
            float cutv = cut[row];
            const float4* rrow = (const float4*)(resF + row * RF_STRIDE);
            #pragma unroll
            for (int nt = 0; nt < 8; ++nt) {
                #pragma unroll
                for (int p = 0; p < 2; ++p) {
                    int k = n_base + nt * 8 + qc + p;
                    float d2a = __fadd_rn(
                        __fadd_rn(rv, __fmul_rn(-2.f, acc[mt][nt][h * 2 + p])), csq[k]);
                    if (d2a <= cutv) {
                        const float4* crow = (const float4*)(C + (size_t)k * DD);
                        float a = 0.f;
                        for (int c = 0; c < 32; ++c) {      // exact: d-ascending fmaf chain
                            float4 cv = __ldg(crow + c);
                            float4 rv4 = rrow[c];
                            a = fmaf(rv4.x, cv.x, a);
                            a = fmaf(rv4.y, cv.y, a);
                            a = fmaf(rv4.z, cv.z, a);
                            a = fmaf(rv4.w, cv.w, a);
                        }
                        float t1  = __fadd_rn(rv, __fmul_rn(-2.0f, a));
                        float d2e = __fadd_rn(t1, csq[k]);
                        unsigned long long pk =
                            ((unsigned long long)ford(d2e) << 32) | (unsigned)k;
                        atomicMin(&cand[row], pk);
                    }
                }
            }
        }
    }
    __syncthreads();

    // ---- outputs: one-hot codes + recon (bit-exact recurrence) ----
    const bool last = (stage == MM - 1);
    float* sstage = side + (size_t)stage * NN * DD;

    #pragma unroll
    for (int rr2 = 0; rr2 < 8; ++rr2) {
        int lrow = wid * 8 + rr2;
        int n    = rowBase + lrow;
        int bidx = (int)(cand[lrow] & 0xffffffffull);

        float* crow_codes = codes + (size_t)n * (MM * KK) + (size_t)stage * KK;
        #pragma unroll
        for (int c = 0; c < 8; ++c) {
            int k = lane + 32 * c;
            crow_codes[k] = (k == bidx) ? 1.0f : 0.0f;
        }

        const float* prow  = prev ? prev + (size_t)n * DD : nullptr;
        const float* cbrow = C + (size_t)bidx * DD;
        float* srow = sstage + (size_t)n * DD;
        float* orow = xrecon + (size_t)n * DD;
        #pragma unroll
        for (int j = 0; j < 4; ++j) {
            int d = lane + 32 * j;
            float cv = __ldg(cbrow + d);
            float pp = prow ? prow[d] : 0.f;
            float v  = __fadd_rn(pp, cv);
            srow[d] = v;
            if (last) orow[d] = v;
        }
    }
}

extern "C" void kernel_launch(void* const* d_in, const int* in_sizes, int n_in,
                              void* d_out, int out_size)
{
    (void)in_sizes; (void)n_in; (void)out_size;
    const float* x  = (const float*)d_in[0];            // (N, D)
    const float* cb = (const float*)d_in[1];            // (M, K, D)

    float* out    = (float*)d_out;
    float* xrecon = out;                                // (N, D)
    float* codes  = out + (size_t)NN * DD;              // (N, M, K)
    float* side   = codes + (size_t)NN * MM * KK;       // (M, N, D)

    cudaFuncSetAttribute(rq_stage_kernel,
                         cudaFuncAttributeMaxDynamicSharedMemorySize, SM_BYTES);

    csq_prep_kernel<<<MM, KK>>>(cb);

    const int grid = NN / BM;   // 512
    for (int i = 0; i < MM; ++i) {
        rq_stage_kernel<<<grid, THREADS, SM_BYTES>>>(
            x, cb + (size_t)i * KK * DD, codes, side, xrecon, i);
    }
}